// round 9
// baseline (speedup 1.0000x reference)
#include <cuda_runtime.h>

#define BATCH 16384
#define CTX   10
#define MAXC  24
#define EMBED 128
#define WPB   8
#define THREADS (WPB * 32)
#define GRID  ((BATCH + WPB - 1) / WPB)   // 2048
#define PITCH 36   // STS banks (4l+i)%32 distinct; 144B rows, 16B-aligned, LDS.128 conflict-free

__global__ void zero_out_kernel(float* out) {
    if (threadIdx.x == 0) out[0] = 0.0f;
}

// Predicated vector gather: @p LDG.E.128, no branch; e stays 0 when pred==0.
__device__ __forceinline__ float4 pred_ldg128(const float4* addr, int pred) {
    float4 e = make_float4(0.f, 0.f, 0.f, 0.f);
    asm("{\n\t"
        ".reg .pred p;\n\t"
        "setp.ne.s32 p, %4, 0;\n\t"
        "@p ld.global.nc.v4.f32 {%0,%1,%2,%3}, [%5];\n\t"
        "}"
        : "+f"(e.x), "+f"(e.y), "+f"(e.z), "+f"(e.w)
        : "r"(pred), "l"(addr));
    return e;
}

// Issue one batch of 8 node gathers; indices come from lane registers via
// shuffle (no memory access on the index path).
__device__ __forceinline__ void issue_batch_shfl(float4 E[8], int pl, int ml,
                                                 int h, const float* W_internal,
                                                 int lane) {
    #pragma unroll
    for (int k = 0; k < 8; k++) {
        const int node = __shfl_sync(0xffffffffu, pl, h * 8 + k);
        const int mk   = __shfl_sync(0xffffffffu, ml, h * 8 + k);
        E[k] = pred_ldg128(reinterpret_cast<const float4*>(
                               W_internal + (long)node * EMBED) + lane,
                           mk);
    }
}

__device__ __forceinline__ void consume_batch(const float4 E[8], float4 v,
                                              float* ws, int h, int lane) {
    #pragma unroll
    for (int k = 0; k < 8; k++) {
        const float pt = fmaf(v.x, E[k].x,
                         fmaf(v.y, E[k].y,
                         fmaf(v.z, E[k].z, v.w * E[k].w)));
        ws[(h * 8 + k) * PITCH + lane] = pt;   // conflict-free STS
    }
}

__global__ __launch_bounds__(THREADS, 5)   // 51-reg cap
void cbow_hs_kernel(const int* __restrict__ context_words,
                    const int* __restrict__ paths,
                    const int* __restrict__ codes,
                    const int* __restrict__ mask,     // int32 0/1
                    const float* __restrict__ W_in,
                    const float* __restrict__ W_internal,
                    float* __restrict__ out)
{
    const int warp_id = threadIdx.x >> 5;
    const int lane    = threadIdx.x & 31;
    const int row     = blockIdx.x * WPB + warp_id;

    __shared__ float wsum[WPB][MAXC * PITCH];   // 27.6 KB
    __shared__ float warp_loss[WPB];

    float contrib = 0.0f;

    if (row < BATCH) {
        float* ws = wsum[warp_id];

        // ---- Entry: ALL per-row indices in one overlapped round trip.
        // Lane j (<24) owns step j's path/mask/code for the whole kernel;
        // batches fetch them by shuffle, phase 3 uses them directly.
        const int li = (lane < MAXC) ? lane : (MAXC - 1);   // clamp: avoid OOB on last row
        int pl = __ldg(paths + row * MAXC + li);
        int ml = __ldg(mask  + row * MAXC + li);
        const int cj = __ldg(codes + row * MAXC + li);

        // ---- Batch 0 issued immediately (waits only on pl/ml arrival);
        // its gather RT runs in parallel with the context gathers below.
        float4 E[8];
        issue_batch_shfl(E, pl, ml, 0, W_internal, lane);

        // ---- Phase 1: context vector (mean of 10 gathered 512B rows).
        const int* cw = context_words + row * CTX;
        float4 v = make_float4(0.f, 0.f, 0.f, 0.f);
        #pragma unroll
        for (int i = 0; i < CTX; i++) {
            const int w = cw[i];
            const float4 e = __ldg(reinterpret_cast<const float4*>(
                                       W_in + (long)w * EMBED) + lane);
            v.x += e.x; v.y += e.y; v.z += e.z; v.w += e.w;
        }
        const float inv_ctx = 1.0f / (float)CTX;
        v.x *= inv_ctx; v.y *= inv_ctx; v.z *= inv_ctx; v.w *= inv_ctx;

        // ---- Phase 2: consume/issue pipeline; index path is shuffle-only.
        consume_batch(E, v, ws, 0, lane);
        issue_batch_shfl(E, pl, ml, 1, W_internal, lane);
        consume_batch(E, v, ws, 1, lane);
        issue_batch_shfl(E, pl, ml, 2, W_internal, lane);
        consume_batch(E, v, ws, 2, lane);
        __syncwarp();

        // ---- Phase 3: lane j (<24) sums step j's 32 partials via 8x LDS.128.
        // No global loads left on the tail: cj/ml are already in registers.
        if (lane < MAXC) {
            const float4* rp = reinterpret_cast<const float4*>(ws + lane * PITCH);
            float4 a0 = rp[0], a1 = rp[1], a2 = rp[2], a3 = rp[3];
            const float4 b0 = rp[4], b1 = rp[5], b2 = rp[6], b3 = rp[7];
            a0.x += b0.x; a0.y += b0.y; a0.z += b0.z; a0.w += b0.w;
            a1.x += b1.x; a1.y += b1.y; a1.z += b1.z; a1.w += b1.w;
            a2.x += b2.x; a2.y += b2.y; a2.z += b2.z; a2.w += b2.w;
            a3.x += b3.x; a3.y += b3.y; a3.z += b3.z; a3.w += b3.w;
            float s = ((a0.x + a0.y) + (a0.z + a0.w))
                    + ((a1.x + a1.y) + (a1.z + a1.w))
                    + ((a2.x + a2.y) + (a2.z + a2.w))
                    + ((a3.x + a3.y) + (a3.z + a3.w));

            const float sign = (float)(2 * cj - 1);
            const float x = -sign * s;
            // softplus(x) = max(x,0) + log(1 + exp(-|x|)), MUFU fast path
            const float sp = fmaxf(x, 0.0f) + __logf(1.0f + __expf(-fabsf(x)));
            contrib = ml ? sp : 0.0f;
        }
    }

    // ---- R4 reduction (measured optimum): shuffles -> smem -> one atomicAdd.
    contrib += __shfl_xor_sync(0xffffffffu, contrib, 16);
    contrib += __shfl_xor_sync(0xffffffffu, contrib, 8);
    contrib += __shfl_xor_sync(0xffffffffu, contrib, 4);
    contrib += __shfl_xor_sync(0xffffffffu, contrib, 2);
    contrib += __shfl_xor_sync(0xffffffffu, contrib, 1);

    if (lane == 0) warp_loss[warp_id] = contrib;
    __syncthreads();

    if (warp_id == 0) {
        float s = (lane < WPB) ? warp_loss[lane] : 0.0f;
        s += __shfl_xor_sync(0xffffffffu, s, 4);
        s += __shfl_xor_sync(0xffffffffu, s, 2);
        s += __shfl_xor_sync(0xffffffffu, s, 1);
        if (lane == 0) atomicAdd(out, s * (1.0f / (float)BATCH));
    }
}

extern "C" void kernel_launch(void* const* d_in, const int* in_sizes, int n_in,
                              void* d_out, int out_size)
{
    const int*   context_words = (const int*)d_in[0];
    const int*   paths         = (const int*)d_in[1];
    const int*   codes         = (const int*)d_in[2];
    const int*   mask          = (const int*)d_in[3];
    const float* W_in          = (const float*)d_in[4];
    const float* W_internal    = (const float*)d_in[5];
    float*       out           = (float*)d_out;

    zero_out_kernel<<<1, 32>>>(out);

    cbow_hs_kernel<<<GRID, THREADS>>>(context_words, paths, codes, mask,
                                      W_in, W_internal, out);
}

// round 10
// speedup vs baseline: 1.2912x; 1.2912x over previous
#include <cuda_runtime.h>

#define BATCH 16384
#define CTX   10
#define MAXC  24
#define EMBED 128
#define WPB   4
#define THREADS (WPB * 32)               // 128
#define GRID  ((BATCH + WPB - 1) / WPB)  // 4096
#define PITCH 36   // STS banks (4l+i)%32 distinct; 144B rows, 16B-aligned, LDS.128 conflict-free

__global__ void zero_out_kernel(float* out) {
    if (threadIdx.x == 0) out[0] = 0.0f;
}

// Predicated vector gather: @p LDG.E.128, no branch; e stays 0 when pred==0.
__device__ __forceinline__ float4 pred_ldg128(const float4* addr, int pred) {
    float4 e = make_float4(0.f, 0.f, 0.f, 0.f);
    asm("{\n\t"
        ".reg .pred p;\n\t"
        "setp.ne.s32 p, %4, 0;\n\t"
        "@p ld.global.nc.v4.f32 {%0,%1,%2,%3}, [%5];\n\t"
        "}"
        : "+f"(e.x), "+f"(e.y), "+f"(e.z), "+f"(e.w)
        : "r"(pred), "l"(addr));
    return e;
}

__global__ __launch_bounds__(THREADS, 4)   // 128-reg cap; occupancy bought with fewer warps, spent on MLP=34/warp
void cbow_hs_kernel(const int* __restrict__ context_words,
                    const int* __restrict__ paths,
                    const int* __restrict__ codes,
                    const int* __restrict__ mask,     // int32 0/1
                    const float* __restrict__ W_in,
                    const float* __restrict__ W_internal,
                    float* __restrict__ out)
{
    const int warp_id = threadIdx.x >> 5;
    const int lane    = threadIdx.x & 31;
    const int row     = blockIdx.x * WPB + warp_id;

    __shared__ float wsum[WPB][MAXC * PITCH];   // 13.8 KB
    __shared__ float warp_loss[WPB];

    float contrib = 0.0f;

    if (row < BATCH) {
        float* ws = wsum[warp_id];

        // ---- RT1: everything scalar, all overlapped.
        // Per-lane code/mask for phase 3 (one coalesced load each, no
        // shuffles anywhere near the gather address path — R9 lesson).
        const int li  = (lane < MAXC) ? lane : (MAXC - 1);
        const int cj  = __ldg(codes + row * MAXC + li);
        const int mlj = __ldg(mask  + row * MAXC + li);
        // Warp-uniform index vectors for gather predication/addressing.
        const int4* p4 = reinterpret_cast<const int4*>(paths + row * MAXC);
        const int4* m4 = reinterpret_cast<const int4*>(mask  + row * MAXC);
        int4 P[6], M[6];
        #pragma unroll
        for (int q = 0; q < 6; q++) { P[q] = __ldg(p4 + q); M[q] = __ldg(m4 + q); }

        // ---- RT2a: ALL 24 node gathers issued back-to-back (independent;
        // only gated on RT1 indices). 24 LDG.E.128 in flight per warp.
        float4 E[MAXC];
        #pragma unroll
        for (int q = 0; q < 6; q++) {
            const int nodes[4] = {P[q].x, P[q].y, P[q].z, P[q].w};
            const int mks[4]   = {M[q].x, M[q].y, M[q].z, M[q].w};
            #pragma unroll
            for (int k = 0; k < 4; k++)
                E[q * 4 + k] = pred_ldg128(reinterpret_cast<const float4*>(
                                               W_internal + (long)nodes[k] * EMBED) + lane,
                                           mks[k]);
        }

        // ---- RT2b: 10 context gathers, overlapping the node loads in flight.
        const int* cw = context_words + row * CTX;
        float4 v = make_float4(0.f, 0.f, 0.f, 0.f);
        #pragma unroll
        for (int i = 0; i < CTX; i++) {
            const int w = cw[i];
            const float4 e = __ldg(reinterpret_cast<const float4*>(
                                       W_in + (long)w * EMBED) + lane);
            v.x += e.x; v.y += e.y; v.z += e.z; v.w += e.w;
        }
        const float inv_ctx = 1.0f / (float)CTX;
        v.x *= inv_ctx; v.y *= inv_ctx; v.z *= inv_ctx; v.w *= inv_ctx;

        // ---- Consume: distributed dots + conflict-free smem transpose.
        #pragma unroll
        for (int l = 0; l < MAXC; l++) {
            const float pt = fmaf(v.x, E[l].x,
                             fmaf(v.y, E[l].y,
                             fmaf(v.z, E[l].z, v.w * E[l].w)));
            ws[l * PITCH + lane] = pt;
        }
        __syncwarp();

        // ---- Phase 3: lane j (<24) sums step j's 32 partials via 8x LDS.128.
        // Zero global loads on the tail (cj/mlj resident since RT1).
        if (lane < MAXC) {
            const float4* rp = reinterpret_cast<const float4*>(ws + lane * PITCH);
            float4 a0 = rp[0], a1 = rp[1], a2 = rp[2], a3 = rp[3];
            const float4 b0 = rp[4], b1 = rp[5], b2 = rp[6], b3 = rp[7];
            a0.x += b0.x; a0.y += b0.y; a0.z += b0.z; a0.w += b0.w;
            a1.x += b1.x; a1.y += b1.y; a1.z += b1.z; a1.w += b1.w;
            a2.x += b2.x; a2.y += b2.y; a2.z += b2.z; a2.w += b2.w;
            a3.x += b3.x; a3.y += b3.y; a3.z += b3.z; a3.w += b3.w;
            float s = ((a0.x + a0.y) + (a0.z + a0.w))
                    + ((a1.x + a1.y) + (a1.z + a1.w))
                    + ((a2.x + a2.y) + (a2.z + a2.w))
                    + ((a3.x + a3.y) + (a3.z + a3.w));

            const float sign = (float)(2 * cj - 1);
            const float x = -sign * s;
            // softplus(x) = max(x,0) + log(1 + exp(-|x|)), MUFU fast path
            const float sp = fmaxf(x, 0.0f) + __logf(1.0f + __expf(-fabsf(x)));
            contrib = mlj ? sp : 0.0f;
        }
    }

    // ---- R4 reduction (measured optimum): shuffles -> smem -> one atomicAdd.
    contrib += __shfl_xor_sync(0xffffffffu, contrib, 16);
    contrib += __shfl_xor_sync(0xffffffffu, contrib, 8);
    contrib += __shfl_xor_sync(0xffffffffu, contrib, 4);
    contrib += __shfl_xor_sync(0xffffffffu, contrib, 2);
    contrib += __shfl_xor_sync(0xffffffffu, contrib, 1);

    if (lane == 0) warp_loss[warp_id] = contrib;
    __syncthreads();

    if (warp_id == 0) {
        float s = (lane < WPB) ? warp_loss[lane] : 0.0f;
        s += __shfl_xor_sync(0xffffffffu, s, 2);
        s += __shfl_xor_sync(0xffffffffu, s, 1);
        if (lane == 0) atomicAdd(out, s * (1.0f / (float)BATCH));
    }
}

extern "C" void kernel_launch(void* const* d_in, const int* in_sizes, int n_in,
                              void* d_out, int out_size)
{
    const int*   context_words = (const int*)d_in[0];
    const int*   paths         = (const int*)d_in[1];
    const int*   codes         = (const int*)d_in[2];
    const int*   mask          = (const int*)d_in[3];
    const float* W_in          = (const float*)d_in[4];
    const float* W_internal    = (const float*)d_in[5];
    float*       out           = (float*)d_out;

    zero_out_kernel<<<1, 32>>>(out);

    cbow_hs_kernel<<<GRID, THREADS>>>(context_words, paths, codes, mask,
                                      W_in, W_internal, out);
}

// round 11
// speedup vs baseline: 1.3957x; 1.0809x over previous
#include <cuda_runtime.h>

#define BATCH 16384
#define CTX   10
#define MAXC  24
#define EMBED 128
#define WPB   8
#define THREADS (WPB * 32)
#define GRID  ((BATCH + WPB - 1) / WPB)   // 2048
#define PITCH 36   // STS banks (4l+i)%32 distinct; 144B rows, 16B-aligned, LDS.128 conflict-free

// Grid-reduction state. Zero-initialized at module load; the last finishing
// block resets both after publishing, so every launch (and every graph
// replay) observes a clean {0, 0}. No allocation, no gpu-scope fence:
// ordering rides on release/acquire ATOMICS (L2-coherent, no CCTL.IVALL).
__device__ float        g_acc;
__device__ unsigned int g_count;

// Predicated vector gather: @p LDG.E.128, no branch; e stays 0 when pred==0.
__device__ __forceinline__ float4 pred_ldg128(const float4* addr, int pred) {
    float4 e = make_float4(0.f, 0.f, 0.f, 0.f);
    asm("{\n\t"
        ".reg .pred p;\n\t"
        "setp.ne.s32 p, %4, 0;\n\t"
        "@p ld.global.nc.v4.f32 {%0,%1,%2,%3}, [%5];\n\t"
        "}"
        : "+f"(e.x), "+f"(e.y), "+f"(e.z), "+f"(e.w)
        : "r"(pred), "l"(addr));
    return e;
}

__global__ __launch_bounds__(THREADS, 6)   // measured optimum: MLP 8/chain @ 6 blocks/SM
void cbow_hs_kernel(const int* __restrict__ context_words,
                    const int* __restrict__ paths,
                    const int* __restrict__ codes,
                    const int* __restrict__ mask,     // int32 0/1
                    const float* __restrict__ W_in,
                    const float* __restrict__ W_internal,
                    float* __restrict__ out)
{
    const int warp_id = threadIdx.x >> 5;
    const int lane    = threadIdx.x & 31;
    const int row     = blockIdx.x * WPB + warp_id;

    __shared__ float wsum[WPB][MAXC * PITCH];   // 27.6 KB
    __shared__ float warp_loss[WPB];

    float contrib = 0.0f;

    if (row < BATCH) {
        float* ws = wsum[warp_id];

        // ---- Entry: per-lane code/mask for the tail (kills the phase-3
        // round trip; validated in R9). Gather indices remain warp-uniform
        // int4 __ldg — NO shuffles on the address path (R9 lesson).
        const int li  = (lane < MAXC) ? lane : (MAXC - 1);
        const int cj  = __ldg(codes + row * MAXC + li);
        const int mlj = __ldg(mask  + row * MAXC + li);

        // ---- Phase 1: context vector (mean of 10 gathered 512B rows).
        const int* cw = context_words + row * CTX;
        float4 v = make_float4(0.f, 0.f, 0.f, 0.f);
        #pragma unroll
        for (int i = 0; i < CTX; i++) {
            const int w = cw[i];
            const float4 e = __ldg(reinterpret_cast<const float4*>(
                                       W_in + (long)w * EMBED) + lane);
            v.x += e.x; v.y += e.y; v.z += e.z; v.w += e.w;
        }
        const float inv_ctx = 1.0f / (float)CTX;
        v.x *= inv_ctx; v.y *= inv_ctx; v.z *= inv_ctx; v.w *= inv_ctx;

        // ---- Phase 2: 24 predicated gathers in 3 batches of 8 (measured
        // optimum); partial dots stored to smem right after each batch.
        const int4* p4 = reinterpret_cast<const int4*>(paths + row * MAXC);
        const int4* m4 = reinterpret_cast<const int4*>(mask  + row * MAXC);

        #pragma unroll
        for (int h = 0; h < 3; h++) {
            const int4 P0 = __ldg(p4 + h * 2), P1 = __ldg(p4 + h * 2 + 1);
            const int4 M0 = __ldg(m4 + h * 2), M1 = __ldg(m4 + h * 2 + 1);
            const int nodes[8] = {P0.x, P0.y, P0.z, P0.w, P1.x, P1.y, P1.z, P1.w};
            const int mks[8]   = {M0.x, M0.y, M0.z, M0.w, M1.x, M1.y, M1.z, M1.w};

            float4 E[8];
            #pragma unroll
            for (int k = 0; k < 8; k++)
                E[k] = pred_ldg128(reinterpret_cast<const float4*>(
                                       W_internal + (long)nodes[k] * EMBED) + lane,
                                   mks[k]);
            #pragma unroll
            for (int k = 0; k < 8; k++) {
                const float pt = fmaf(v.x, E[k].x,
                                 fmaf(v.y, E[k].y,
                                 fmaf(v.z, E[k].z, v.w * E[k].w)));
                ws[(h * 8 + k) * PITCH + lane] = pt;   // conflict-free STS
            }
        }
        __syncwarp();

        // ---- Phase 3: lane j (<24) sums step j's 32 partials via 8x LDS.128.
        // Zero global loads on the tail: cj/mlj resident since entry.
        if (lane < MAXC) {
            const float4* rp = reinterpret_cast<const float4*>(ws + lane * PITCH);
            float4 a0 = rp[0], a1 = rp[1], a2 = rp[2], a3 = rp[3];
            const float4 b0 = rp[4], b1 = rp[5], b2 = rp[6], b3 = rp[7];
            a0.x += b0.x; a0.y += b0.y; a0.z += b0.z; a0.w += b0.w;
            a1.x += b1.x; a1.y += b1.y; a1.z += b1.z; a1.w += b1.w;
            a2.x += b2.x; a2.y += b2.y; a2.z += b2.z; a2.w += b2.w;
            a3.x += b3.x; a3.y += b3.y; a3.z += b3.z; a3.w += b3.w;
            float s = ((a0.x + a0.y) + (a0.z + a0.w))
                    + ((a1.x + a1.y) + (a1.z + a1.w))
                    + ((a2.x + a2.y) + (a2.z + a2.w))
                    + ((a3.x + a3.y) + (a3.z + a3.w));

            const float sign = (float)(2 * cj - 1);
            const float x = -sign * s;
            // softplus(x) = max(x,0) + log(1 + exp(-|x|)), MUFU fast path
            const float sp = fmaxf(x, 0.0f) + __logf(1.0f + __expf(-fabsf(x)));
            contrib = mlj ? sp : 0.0f;
        }
    }

    // ---- Warp + block reduce (R4 measured optimum).
    contrib += __shfl_xor_sync(0xffffffffu, contrib, 16);
    contrib += __shfl_xor_sync(0xffffffffu, contrib, 8);
    contrib += __shfl_xor_sync(0xffffffffu, contrib, 4);
    contrib += __shfl_xor_sync(0xffffffffu, contrib, 2);
    contrib += __shfl_xor_sync(0xffffffffu, contrib, 1);

    if (lane == 0) warp_loss[warp_id] = contrib;
    __syncthreads();

    // ---- Fence-free grid finish: release-atomic on the counter orders this
    // block's g_acc add before its arrival; the last block reads g_acc with
    // an acquire-atomic (+0.0f) straight from L2. No CCTL.IVALL in the hot
    // path (vs R6's __threadfence which cost ~3us of L1 invalidations).
    if (threadIdx.x == 0) {
        float s = 0.0f;
        #pragma unroll
        for (int i = 0; i < WPB; i++) s += warp_loss[i];
        atomicAdd(&g_acc, s);                       // relaxed, L2-coherent

        unsigned int prev;
        asm volatile("atom.release.gpu.add.u32 %0, [%1], 1;"
                     : "=r"(prev) : "l"(&g_count) : "memory");
        if (prev == GRID - 1) {                     // last block: publish + reset
            float total;
            asm volatile("atom.acquire.gpu.add.f32 %0, [%1], 0f00000000;"
                         : "=f"(total) : "l"(&g_acc) : "memory");
            out[0]  = total * (1.0f / (float)BATCH);
            g_acc   = 0.0f;                         // launch boundary orders resets
            g_count = 0u;
        }
    }
}

extern "C" void kernel_launch(void* const* d_in, const int* in_sizes, int n_in,
                              void* d_out, int out_size)
{
    const int*   context_words = (const int*)d_in[0];
    const int*   paths         = (const int*)d_in[1];
    const int*   codes         = (const int*)d_in[2];
    const int*   mask          = (const int*)d_in[3];
    const float* W_in          = (const float*)d_in[4];
    const float* W_internal    = (const float*)d_in[5];
    float*       out           = (float*)d_out;

    cbow_hs_kernel<<<GRID, THREADS>>>(context_words, paths, codes, mask,
                                      W_in, W_internal, out);
}